// round 9
// baseline (speedup 1.0000x reference)
#include <cuda_runtime.h>
#include <math.h>

// ---------------------------------------------------------------------------
// PCasso predictive-coding relaxation, analytically collapsed:
//   so_final ~= x,  E = 0.5 * mean((x4v - x)^2)
// x4v = tanh(W4@x3v+b4), x3v = leaky(W3@x2v+b3), x2v = leaky(W2@x1+b2),
// x1 = leaky(W1[:,0]+b1).
//
// R9: ONE kernel, block-specialized, single wave (848 blocks, all resident):
//   bids 0..63   : chain only (grid barriers among 64), then e=0 reduction
//   bids 64..847 : R5's proven copy loop (8 float4/thread, fixed x4v column),
//                  chain-done wait only AFTER the copy, then energy combine.
// ---------------------------------------------------------------------------

#define N4_I     6422528          // 8192 * 784
#define NF4      1605632          // N4_I / 4
#define CHAIN_B  64
#define COPY_B   784
#define B_GRID   848              // CHAIN_B + COPY_B; <= 888 resident @40regs
#define STRIDE4  200704           // 784*256; % 196 == 0 -> fixed column

__device__ float  g_x2v[512];
__device__ float  g_x3v[1024];
__device__ __align__(16) float g_x4v[784];
__device__ double g_part[B_GRID];
__device__ unsigned g_bar1;       // reset by final block each launch
__device__ unsigned g_bar2;
__device__ unsigned g_chain_done;
__device__ unsigned g_done;

__device__ __forceinline__ float leaky(float v) { return v >= 0.0f ? v : 0.2f * v; }

__device__ __forceinline__ float warp_sum(float v) {
    #pragma unroll
    for (int o = 16; o > 0; o >>= 1) v += __shfl_down_sync(0xffffffffu, v, o);
    return v;
}

// Grid barrier among the CHAIN_B chain blocks only (all co-resident).
__device__ __forceinline__ void grid_bar(unsigned* ctr) {
    __syncthreads();
    if (threadIdx.x == 0) {
        __threadfence();
        atomicAdd(ctr, 1u);
        volatile unsigned* vc = (volatile unsigned*)ctr;
        while (*vc < CHAIN_B) { __nanosleep(40); }
    }
    __syncthreads();
    __threadfence();
}

__global__ void __launch_bounds__(256)
k_fused(const float* __restrict__ x,
        const float* __restrict__ W1, const float* __restrict__ b1,
        const float* __restrict__ W2, const float* __restrict__ b2,
        const float* __restrict__ W3, const float* __restrict__ b3,
        const float* __restrict__ W4, const float* __restrict__ b4,
        float* __restrict__ out) {
    __shared__ float  sh[1024];
    __shared__ double sd[256];
    __shared__ double s_w[8];
    __shared__ int    s_last;
    int t = threadIdx.x, warp = t >> 5, lane = t & 31;
    int b = blockIdx.x;

    float4 sx = make_float4(0.f, 0.f, 0.f, 0.f);
    float sxx = 0.f;
    int c4 = 0;

    if (b < CHAIN_B) {
        // ================= chain (blocks 0..63), copy-free =================
        // stage A: x1 (shared) -> x2v ; 512 rows = warp*64 + b
        sh[t] = leaky(W1[t] + b1[t]);
        __syncthreads();
        {
            int row = warp * 64 + b;
            const float4* w = (const float4*)(W2 + row * 256);
            float s = 0.0f;
            #pragma unroll
            for (int j = lane; j < 64; j += 32) {
                float4 wv = w[j];
                s += wv.x * sh[4*j] + wv.y * sh[4*j+1] + wv.z * sh[4*j+2] + wv.w * sh[4*j+3];
            }
            s = warp_sum(s);
            if (lane == 0) g_x2v[row] = leaky(s + b2[row]);
        }
        grid_bar(&g_bar1);

        // stage B: x2v -> x3v ; 1024 rows, two strided passes
        __syncthreads();
        sh[t] = g_x2v[t];
        sh[t + 256] = g_x2v[t + 256];
        __syncthreads();
        for (int row = warp * 64 + b; row < 1024; row += 512) {
            const float4* w = (const float4*)(W3 + row * 512);
            float s = 0.0f;
            #pragma unroll
            for (int j = lane; j < 128; j += 32) {
                float4 wv = w[j];
                s += wv.x * sh[4*j] + wv.y * sh[4*j+1] + wv.z * sh[4*j+2] + wv.w * sh[4*j+3];
            }
            s = warp_sum(s);
            if (lane == 0) g_x3v[row] = leaky(s + b3[row]);
        }
        grid_bar(&g_bar2);

        // stage C: x3v -> x4v ; 784 rows
        __syncthreads();
        #pragma unroll
        for (int kk = 0; kk < 4; kk++) sh[t + 256 * kk] = g_x3v[t + 256 * kk];
        __syncthreads();
        for (int row = warp * 64 + b; row < 784; row += 512) {
            const float4* w = (const float4*)(W4 + row * 1024);
            float s = 0.0f;
            #pragma unroll
            for (int j = lane; j < 256; j += 32) {
                float4 wv = w[j];
                s += wv.x * sh[4*j] + wv.y * sh[4*j+1] + wv.z * sh[4*j+2] + wv.w * sh[4*j+3];
            }
            s = warp_sum(s);
            if (lane == 0) g_x4v[row] = tanhf(s + b4[row]);
        }
        __threadfence();
        __syncthreads();
        if (t == 0) atomicAdd(&g_chain_done, 1u);
    } else {
        // ================= copy (blocks 64..847): R5 loop ==================
        const float4* x4p = (const float4*)x;
        float4* o4 = (float4*)out;
        int gtid = (b - CHAIN_B) * 256 + t;
        c4 = gtid % 196;                     // fixed for all 8 iterations
        float lastw = 0.f;

        #pragma unroll
        for (int i = 0; i < 8; i++) {
            int k = gtid + i * STRIDE4;
            float4 xb = __ldg(&x4p[k]);

            float prev = __shfl_up_sync(0xffffffffu, xb.w, 1);
            if (lane == 0) prev = __ldg(&x[max(4*k - 1, 0)]);   // out[0]=E later
            o4[k] = make_float4(prev, xb.x, xb.y, xb.z);
            lastw = xb.w;

            sx.x += xb.x; sx.y += xb.y; sx.z += xb.z; sx.w += xb.w;
            sxx = fmaf(xb.x, xb.x, sxx);
            sxx = fmaf(xb.y, xb.y, sxx);
            sxx = fmaf(xb.z, xb.z, sxx);
            sxx = fmaf(xb.w, xb.w, sxx);
        }
        if (gtid == STRIDE4 - 1) out[N4_I] = lastw;   // tail (k = NF4-1)
    }

    // ===================== wait for chain, combine energy =============
    if (t == 0) {
        volatile unsigned* vc = (volatile unsigned*)&g_chain_done;
        while (*vc < CHAIN_B) { __nanosleep(40); }
    }
    __syncthreads();
    __threadfence();

    float e = 0.0f;
    if (b >= CHAIN_B) {
        const float4* x4v4 = (const float4*)g_x4v;
        float4 v = x4v4[c4];
        // closed-form per-thread energy: sum_c [8 v_c^2 - 2 v_c sx_c] + sxx
        e = sxx;
        e = fmaf(v.x, fmaf(8.f, v.x, -2.f * sx.x), e);
        e = fmaf(v.y, fmaf(8.f, v.y, -2.f * sx.y), e);
        e = fmaf(v.z, fmaf(8.f, v.z, -2.f * sx.z), e);
        e = fmaf(v.w, fmaf(8.f, v.w, -2.f * sx.w), e);
    }

    // deterministic block reduce
    e = warp_sum(e);
    if (lane == 0) s_w[warp] = (double)e;
    __syncthreads();
    if (t == 0) {
        double s = 0.0;
        #pragma unroll
        for (int i = 0; i < 8; i++) s += s_w[i];
        g_part[b] = s;
        __threadfence();
        unsigned r = atomicAdd(&g_done, 1u);
        s_last = (r == B_GRID - 1) ? 1 : 0;
    }
    __syncthreads();

    if (s_last) {                         // final block: global reduce
        __threadfence();
        double a = 0.0;
        for (int i = t; i < B_GRID; i += 256) a += g_part[i];
        sd[t] = a;
        __syncthreads();
        #pragma unroll
        for (int s = 128; s > 0; s >>= 1) {
            if (t < s) sd[t] += sd[t + s];
            __syncthreads();
        }
        if (t == 0) {
            out[0] = (float)(0.5 * sd[0] / 6422528.0);
            g_bar1 = 0u; g_bar2 = 0u;     // reset for next replay
            g_chain_done = 0u;
            g_done = 0u;
        }
    }
}

extern "C" void kernel_launch(void* const* d_in, const int* in_sizes, int n_in,
                              void* d_out, int out_size) {
    const float* x    = (const float*)d_in[0];
    const float* W1   = (const float*)d_in[2];
    const float* b1   = (const float*)d_in[3];
    const float* W2   = (const float*)d_in[4];
    const float* b2   = (const float*)d_in[5];
    const float* W3   = (const float*)d_in[6];
    const float* b3   = (const float*)d_in[7];
    const float* W4   = (const float*)d_in[8];
    const float* b4   = (const float*)d_in[9];
    float* out = (float*)d_out;

    k_fused<<<B_GRID, 256>>>(x, W1, b1, W2, b2, W3, b3, W4, b4, out);
}

// round 10
// speedup vs baseline: 1.0770x; 1.0770x over previous
#include <cuda_runtime.h>
#include <math.h>

// ---------------------------------------------------------------------------
// PCasso predictive-coding relaxation, analytically collapsed:
//   so_final ~= x,  E = 0.5 * mean((x4v - x)^2)
// x4v = tanh(W4@x3v+b4), x3v = leaky(W3@x2v+b3), x2v = leaky(W2@x1+b2),
// x1 = leaky(W1[:,0]+b1).
//
// R10 = R9 (block-specialized single kernel) + __launch_bounds__(256,6):
// caps regs at 42 -> 6 blocks/SM -> 888 resident slots >= 848 grid ->
// SINGLE WAVE (R9 compiled to 70 regs -> 3/SM -> two waves -> regression).
//   bids 0..63   : chain only (grid barriers among 64)
//   bids 64..847 : copy loop (8 float4/thread, fixed x4v column), then
//                  chain-done wait, energy combine, global reduce.
// ---------------------------------------------------------------------------

#define N4_I     6422528          // 8192 * 784
#define NF4      1605632          // N4_I / 4
#define CHAIN_B  64
#define B_GRID   848              // 64 + 784; <= 888 resident at 6 blocks/SM
#define STRIDE4  200704           // 784*256; % 196 == 0 -> fixed column

__device__ float  g_x2v[512];
__device__ float  g_x3v[1024];
__device__ __align__(16) float g_x4v[784];
__device__ double g_part[B_GRID];
__device__ unsigned g_bar1;       // reset by final block each launch
__device__ unsigned g_bar2;
__device__ unsigned g_chain_done;
__device__ unsigned g_done;

__device__ __forceinline__ float leaky(float v) { return v >= 0.0f ? v : 0.2f * v; }

__device__ __forceinline__ float warp_sum(float v) {
    #pragma unroll
    for (int o = 16; o > 0; o >>= 1) v += __shfl_down_sync(0xffffffffu, v, o);
    return v;
}

// Grid barrier among the CHAIN_B chain blocks only (all co-resident).
__device__ __forceinline__ void grid_bar(unsigned* ctr) {
    __syncthreads();
    if (threadIdx.x == 0) {
        __threadfence();
        atomicAdd(ctr, 1u);
        volatile unsigned* vc = (volatile unsigned*)ctr;
        while (*vc < CHAIN_B) { __nanosleep(32); }
    }
    __syncthreads();
    __threadfence();
}

__global__ void __launch_bounds__(256, 6)
k_fused(const float* __restrict__ x,
        const float* __restrict__ W1, const float* __restrict__ b1,
        const float* __restrict__ W2, const float* __restrict__ b2,
        const float* __restrict__ W3, const float* __restrict__ b3,
        const float* __restrict__ W4, const float* __restrict__ b4,
        float* __restrict__ out) {
    __shared__ float  sh[1024];
    __shared__ double sd[256];
    __shared__ double s_w[8];
    __shared__ int    s_last;
    int t = threadIdx.x, warp = t >> 5, lane = t & 31;
    int b = blockIdx.x;

    float4 sx = make_float4(0.f, 0.f, 0.f, 0.f);
    float sxx = 0.f;
    int c4 = 0;

    if (b < CHAIN_B) {
        // ================= chain (blocks 0..63), copy-free =================
        // stage A: x1 (shared) -> x2v ; 512 rows = warp*64 + b
        sh[t] = leaky(W1[t] + b1[t]);
        __syncthreads();
        {
            int row = warp * 64 + b;
            const float4* w = (const float4*)(W2 + row * 256);
            float s = 0.0f;
            #pragma unroll
            for (int j = lane; j < 64; j += 32) {
                float4 wv = w[j];
                s += wv.x * sh[4*j] + wv.y * sh[4*j+1] + wv.z * sh[4*j+2] + wv.w * sh[4*j+3];
            }
            s = warp_sum(s);
            if (lane == 0) g_x2v[row] = leaky(s + b2[row]);
        }
        grid_bar(&g_bar1);

        // stage B: x2v -> x3v ; 1024 rows, two strided passes
        __syncthreads();
        sh[t] = g_x2v[t];
        sh[t + 256] = g_x2v[t + 256];
        __syncthreads();
        for (int row = warp * 64 + b; row < 1024; row += 512) {
            const float4* w = (const float4*)(W3 + row * 512);
            float s = 0.0f;
            #pragma unroll
            for (int j = lane; j < 128; j += 32) {
                float4 wv = w[j];
                s += wv.x * sh[4*j] + wv.y * sh[4*j+1] + wv.z * sh[4*j+2] + wv.w * sh[4*j+3];
            }
            s = warp_sum(s);
            if (lane == 0) g_x3v[row] = leaky(s + b3[row]);
        }
        grid_bar(&g_bar2);

        // stage C: x3v -> x4v ; 784 rows
        __syncthreads();
        #pragma unroll
        for (int kk = 0; kk < 4; kk++) sh[t + 256 * kk] = g_x3v[t + 256 * kk];
        __syncthreads();
        for (int row = warp * 64 + b; row < 784; row += 512) {
            const float4* w = (const float4*)(W4 + row * 1024);
            float s = 0.0f;
            #pragma unroll
            for (int j = lane; j < 256; j += 32) {
                float4 wv = w[j];
                s += wv.x * sh[4*j] + wv.y * sh[4*j+1] + wv.z * sh[4*j+2] + wv.w * sh[4*j+3];
            }
            s = warp_sum(s);
            if (lane == 0) g_x4v[row] = tanhf(s + b4[row]);
        }
        __threadfence();
        __syncthreads();
        if (t == 0) atomicAdd(&g_chain_done, 1u);
    } else {
        // ================= copy (blocks 64..847): R5 loop ==================
        const float4* x4p = (const float4*)x;
        float4* o4 = (float4*)out;
        int gtid = (b - CHAIN_B) * 256 + t;
        c4 = gtid % 196;                     // fixed for all 8 iterations
        float lastw = 0.f;

        #pragma unroll
        for (int i = 0; i < 8; i++) {
            int k = gtid + i * STRIDE4;
            float4 xb = __ldg(&x4p[k]);

            float prev = __shfl_up_sync(0xffffffffu, xb.w, 1);
            if (lane == 0) prev = __ldg(&x[max(4*k - 1, 0)]);   // out[0]=E later
            o4[k] = make_float4(prev, xb.x, xb.y, xb.z);
            lastw = xb.w;

            sx.x += xb.x; sx.y += xb.y; sx.z += xb.z; sx.w += xb.w;
            sxx = fmaf(xb.x, xb.x, sxx);
            sxx = fmaf(xb.y, xb.y, sxx);
            sxx = fmaf(xb.z, xb.z, sxx);
            sxx = fmaf(xb.w, xb.w, sxx);
        }
        if (gtid == STRIDE4 - 1) out[N4_I] = lastw;   // tail (k = NF4-1)
    }

    // ===================== wait for chain, combine energy =============
    if (t == 0) {
        volatile unsigned* vc = (volatile unsigned*)&g_chain_done;
        while (*vc < CHAIN_B) { __nanosleep(32); }
    }
    __syncthreads();
    __threadfence();

    float e = 0.0f;
    if (b >= CHAIN_B) {
        const float4* x4v4 = (const float4*)g_x4v;
        float4 v = x4v4[c4];
        // closed-form per-thread energy: sum_c [8 v_c^2 - 2 v_c sx_c] + sxx
        e = sxx;
        e = fmaf(v.x, fmaf(8.f, v.x, -2.f * sx.x), e);
        e = fmaf(v.y, fmaf(8.f, v.y, -2.f * sx.y), e);
        e = fmaf(v.z, fmaf(8.f, v.z, -2.f * sx.z), e);
        e = fmaf(v.w, fmaf(8.f, v.w, -2.f * sx.w), e);
    }

    // deterministic block reduce
    e = warp_sum(e);
    if (lane == 0) s_w[warp] = (double)e;
    __syncthreads();
    if (t == 0) {
        double s = 0.0;
        #pragma unroll
        for (int i = 0; i < 8; i++) s += s_w[i];
        g_part[b] = s;
        __threadfence();
        unsigned r = atomicAdd(&g_done, 1u);
        s_last = (r == B_GRID - 1) ? 1 : 0;
    }
    __syncthreads();

    if (s_last) {                         // final block: global reduce
        __threadfence();
        double a = 0.0;
        for (int i = t; i < B_GRID; i += 256) a += g_part[i];
        sd[t] = a;
        __syncthreads();
        #pragma unroll
        for (int s = 128; s > 0; s >>= 1) {
            if (t < s) sd[t] += sd[t + s];
            __syncthreads();
        }
        if (t == 0) {
            out[0] = (float)(0.5 * sd[0] / 6422528.0);
            g_bar1 = 0u; g_bar2 = 0u;     // reset for next replay
            g_chain_done = 0u;
            g_done = 0u;
        }
    }
}

extern "C" void kernel_launch(void* const* d_in, const int* in_sizes, int n_in,
                              void* d_out, int out_size) {
    const float* x    = (const float*)d_in[0];
    const float* W1   = (const float*)d_in[2];
    const float* b1   = (const float*)d_in[3];
    const float* W2   = (const float*)d_in[4];
    const float* b2   = (const float*)d_in[5];
    const float* W3   = (const float*)d_in[6];
    const float* b3   = (const float*)d_in[7];
    const float* W4   = (const float*)d_in[8];
    const float* b4   = (const float*)d_in[9];
    float* out = (float*)d_out;

    k_fused<<<B_GRID, 256>>>(x, W1, b1, W2, b2, W3, b3, W4, b4, out);
}